// round 7
// baseline (speedup 1.0000x reference)
#include <cuda_runtime.h>

#define Bdim 16
#define Tdim 1024
#define Cdim 1024
#define T2 (Tdim + 2)
#define NROWS (Bdim * T2)
#define EPS 1e-5f
#define NT 128         // threads per CTA (4 warps per row)
#define VPT 2          // float4 per thread: 128*2*4 = 1024 channels
#define RPC 8          // sequential rows per CTA (amortizes gamma/beta regs)

// CTA-per-row, 8 rows per CTA. gamma/beta of the final LN persist in registers
// across rows: per-row L1 traffic drops from 20KB to 12KB.

__device__ __forceinline__ float2 row_reduce128(float s, float s2, volatile float* sm) {
    const int lane = threadIdx.x & 31;
    const int w    = threadIdx.x >> 5;
    #pragma unroll
    for (int o = 16; o > 0; o >>= 1) {
        s  += __shfl_xor_sync(0xffffffffu, s,  o);
        s2 += __shfl_xor_sync(0xffffffffu, s2, o);
    }
    __syncthreads();               // protect smem from previous iteration
    if (lane == 0) { sm[w * 2] = s; sm[w * 2 + 1] = s2; }
    __syncthreads();
    return make_float2(sm[0] + sm[2] + sm[4] + sm[6],
                       sm[1] + sm[3] + sm[5] + sm[7]);
}

__global__ void __launch_bounds__(NT)
embed_kernel(const float* __restrict__ x,
             const int*   __restrict__ lengths,
             const float* __restrict__ bos_emb,
             const float* __restrict__ eos_emb,
             const float* __restrict__ ln_s_g,
             const float* __restrict__ ln_s_b,
             const float* __restrict__ pos_table,
             const float* __restrict__ scale_p,
             const float* __restrict__ ln_e_g,
             const float* __restrict__ ln_e_b,
             float* __restrict__ out,
             long long out_size) {
    const int tid  = threadIdx.x;
    const int row0 = blockIdx.x * RPC;
    const float sc = scale_p[0];

    __shared__ float sm[8];

    // Persist final-LN gamma/beta in registers for all RPC rows (8 regs each)
    float4 g[VPT], bt[VPT];
    {
        const float4* gg = reinterpret_cast<const float4*>(ln_e_g);
        const float4* bb = reinterpret_cast<const float4*>(ln_e_b);
        #pragma unroll
        for (int c = 0; c < VPT; c++) {
            g[c]  = gg[tid + NT * c];
            bt[c] = bb[tid + NT * c];
        }
    }

    const long long XSZ = (long long)NROWS * Cdim;
    const bool aux  = (out_size >= XSZ + (long long)NROWS);
    const bool aux2 = (out_size >= XSZ + (long long)NROWS + Bdim);

    #pragma unroll 1
    for (int r = 0; r < RPC; r++) {
        const int row = row0 + r;
        if (row >= NROWS) break;
        const int b  = row / T2;
        const int t2 = row % T2;
        const int l  = lengths[b];

        float4 v[VPT];

        if (t2 == 0 || t2 == l + 1) {
            // Inline layernorm of the special embedding (~32 of 16416 rows)
            const float4* src = reinterpret_cast<const float4*>((t2 == 0) ? bos_emb : eos_emb);
            float s = 0.f, s2 = 0.f;
            #pragma unroll
            for (int c = 0; c < VPT; c++) {
                v[c] = src[tid + NT * c];
                s  += v[c].x + v[c].y + v[c].z + v[c].w;
                s2 += v[c].x*v[c].x + v[c].y*v[c].y + v[c].z*v[c].z + v[c].w*v[c].w;
            }
            const float2 rr = row_reduce128(s, s2, sm);
            const float mu  = rr.x * (1.0f / Cdim);
            const float var = rr.y * (1.0f / Cdim) - mu * mu;
            const float inv = rsqrtf(var + EPS);
            const float4* sg = reinterpret_cast<const float4*>(ln_s_g);
            const float4* sb = reinterpret_cast<const float4*>(ln_s_b);
            #pragma unroll
            for (int c = 0; c < VPT; c++) {
                const float4 gs = sg[tid + NT * c];
                const float4 bs = sb[tid + NT * c];
                v[c].x = (v[c].x - mu) * inv * gs.x + bs.x;
                v[c].y = (v[c].y - mu) * inv * gs.y + bs.y;
                v[c].z = (v[c].z - mu) * inv * gs.z + bs.z;
                v[c].w = (v[c].w - mu) * inv * gs.w + bs.w;
            }
        } else if (t2 >= 1 && t2 <= l) {
            const float4* xr = reinterpret_cast<const float4*>(
                x + ((size_t)(b * Tdim + (t2 - 1))) * Cdim);
            #pragma unroll
            for (int c = 0; c < VPT; c++) v[c] = xr[tid + NT * c];
        } else {
            #pragma unroll
            for (int c = 0; c < VPT; c++) v[c] = make_float4(0.f, 0.f, 0.f, 0.f);
        }

        // Positional embedding: nonpad -> row t2+2, pad -> PAD_IDX row (1)
        const int pos = (t2 < l + 2) ? (t2 + 2) : 1;
        const float4* per = reinterpret_cast<const float4*>(pos_table + (size_t)pos * Cdim);

        float s = 0.f, s2 = 0.f;
        #pragma unroll
        for (int c = 0; c < VPT; c++) {
            const float4 p = per[tid + NT * c];
            v[c].x = v[c].x * sc + p.x;
            v[c].y = v[c].y * sc + p.y;
            v[c].z = v[c].z * sc + p.z;
            v[c].w = v[c].w * sc + p.w;
            s  += v[c].x + v[c].y + v[c].z + v[c].w;
            s2 += v[c].x*v[c].x + v[c].y*v[c].y + v[c].z*v[c].z + v[c].w*v[c].w;
        }
        const float2 rr = row_reduce128(s, s2, sm);
        const float mu  = rr.x * (1.0f / Cdim);
        const float var = rr.y * (1.0f / Cdim) - mu * mu;
        const float inv = rsqrtf(var + EPS);

        float4* orow = reinterpret_cast<float4*>(out + (size_t)row * Cdim);
        #pragma unroll
        for (int c = 0; c < VPT; c++) {
            float4 o;
            o.x = (v[c].x - mu) * inv * g[c].x + bt[c].x;
            o.y = (v[c].y - mu) * inv * g[c].y + bt[c].y;
            o.z = (v[c].z - mu) * inv * g[c].z + bt[c].z;
            o.w = (v[c].w - mu) * inv * g[c].w + bt[c].w;
            orow[tid + NT * c] = o;
        }

        // Auxiliary outputs appended after the main tensor if the buffer has room
        if (aux) {
            if (tid == 0) out[XSZ + row] = (t2 >= l + 2) ? 1.0f : 0.0f;
            if (tid == 1 && t2 == 0 && aux2)
                out[XSZ + (long long)NROWS + b] = (float)(l + 2);
        }
    }
}

extern "C" void kernel_launch(void* const* d_in, const int* in_sizes, int n_in,
                              void* d_out, int out_size) {
    const float* x         = (const float*)d_in[0];
    const int*   lengths   = (const int*)  d_in[1];
    const float* bos_emb   = (const float*)d_in[2];
    const float* eos_emb   = (const float*)d_in[3];
    const float* ln_s_g    = (const float*)d_in[4];
    const float* ln_s_b    = (const float*)d_in[5];
    const float* pos_table = (const float*)d_in[6];
    const float* scale     = (const float*)d_in[7];
    const float* ln_e_g    = (const float*)d_in[8];
    const float* ln_e_b    = (const float*)d_in[9];
    float* out = (float*)d_out;

    const int grid = (NROWS + RPC - 1) / RPC;   // 2052
    embed_kernel<<<grid, NT>>>(
        x, lengths, bos_emb, eos_emb, ln_s_g, ln_s_b,
        pos_table, scale, ln_e_g, ln_e_b, out, (long long)out_size);
}

// round 8
// speedup vs baseline: 1.1889x; 1.1889x over previous
#include <cuda_runtime.h>

#define Bdim 16
#define Tdim 1024
#define Cdim 1024
#define T2 (Tdim + 2)
#define NROWS (Bdim * T2)
#define EPS 1e-5f
#define NT 64          // threads per CTA (one row per CTA, 2 warps)
#define VPT 4          // float4 per thread: 64*4*4 = 1024 channels

// Precomputed rows (allocation-free __device__ scratch)
__device__ float g_eos_ln[Cdim];    // LN(eos_emb; ln_s)
__device__ float g_bos_out[Cdim];   // LN( LN(bos;ln_s)*sc + pe[2] ; ln_e )  — all BOS rows
__device__ float g_pad_out[Cdim];   // LN( pe[1] ; ln_e )                    — all pad rows

__device__ __forceinline__ float2 row_reduce64(float s, float s2, volatile float* sm) {
    const int lane = threadIdx.x & 31;
    const int w    = threadIdx.x >> 5;
    #pragma unroll
    for (int o = 16; o > 0; o >>= 1) {
        s  += __shfl_xor_sync(0xffffffffu, s,  o);
        s2 += __shfl_xor_sync(0xffffffffu, s2, o);
    }
    __syncthreads();
    if (lane == 0) { sm[w * 2] = s; sm[w * 2 + 1] = s2; }
    __syncthreads();
    return make_float2(sm[0] + sm[2], sm[1] + sm[3]);
}

// Layernorm of a register-resident row fragment (64 threads, 4 float4 each)
__device__ __forceinline__ void ln_frag(float4 (&v)[VPT],
                                        const float* __restrict__ gamma,
                                        const float* __restrict__ beta,
                                        volatile float* sm, int tid) {
    float s = 0.f, s2 = 0.f;
    #pragma unroll
    for (int c = 0; c < VPT; c++) {
        s  += v[c].x + v[c].y + v[c].z + v[c].w;
        s2 += v[c].x*v[c].x + v[c].y*v[c].y + v[c].z*v[c].z + v[c].w*v[c].w;
    }
    const float2 r = row_reduce64(s, s2, sm);
    const float mu  = r.x * (1.0f / Cdim);
    const float var = r.y * (1.0f / Cdim) - mu * mu;
    const float inv = rsqrtf(var + EPS);
    const float4* gg = reinterpret_cast<const float4*>(gamma);
    const float4* bb = reinterpret_cast<const float4*>(beta);
    #pragma unroll
    for (int c = 0; c < VPT; c++) {
        const float4 g = gg[tid + NT * c];
        const float4 b = bb[tid + NT * c];
        v[c].x = (v[c].x - mu) * inv * g.x + b.x;
        v[c].y = (v[c].y - mu) * inv * g.y + b.y;
        v[c].z = (v[c].z - mu) * inv * g.z + b.z;
        v[c].w = (v[c].w - mu) * inv * g.w + b.w;
    }
}

// Kernel A: precompute eos_ln, bos_out, pad_out (3 tiny CTAs)
__global__ void __launch_bounds__(NT)
precompute_kernel(const float* __restrict__ bos_emb,
                  const float* __restrict__ eos_emb,
                  const float* __restrict__ ln_s_g,
                  const float* __restrict__ ln_s_b,
                  const float* __restrict__ pos_table,
                  const float* __restrict__ scale_p,
                  const float* __restrict__ ln_e_g,
                  const float* __restrict__ ln_e_b) {
    __shared__ float sm[4];
    const int tid = threadIdx.x;
    float4 v[VPT];

    if (blockIdx.x == 0) {
        // g_bos_out = LN( LN(bos;ln_s)*sc + pe[2] ; ln_e )
        const float4* src = reinterpret_cast<const float4*>(bos_emb);
        #pragma unroll
        for (int c = 0; c < VPT; c++) v[c] = src[tid + NT * c];
        ln_frag(v, ln_s_g, ln_s_b, sm, tid);
        const float sc = scale_p[0];
        const float4* pe = reinterpret_cast<const float4*>(pos_table + 2 * (size_t)Cdim);
        #pragma unroll
        for (int c = 0; c < VPT; c++) {
            const float4 p = pe[tid + NT * c];
            v[c].x = v[c].x * sc + p.x;
            v[c].y = v[c].y * sc + p.y;
            v[c].z = v[c].z * sc + p.z;
            v[c].w = v[c].w * sc + p.w;
        }
        ln_frag(v, ln_e_g, ln_e_b, sm, tid);
        #pragma unroll
        for (int c = 0; c < VPT; c++)
            reinterpret_cast<float4*>(g_bos_out)[tid + NT * c] = v[c];
    } else if (blockIdx.x == 1) {
        // g_eos_ln = LN(eos; ln_s)
        const float4* src = reinterpret_cast<const float4*>(eos_emb);
        #pragma unroll
        for (int c = 0; c < VPT; c++) v[c] = src[tid + NT * c];
        ln_frag(v, ln_s_g, ln_s_b, sm, tid);
        #pragma unroll
        for (int c = 0; c < VPT; c++)
            reinterpret_cast<float4*>(g_eos_ln)[tid + NT * c] = v[c];
    } else {
        // g_pad_out = LN( pe[1] ; ln_e )   (x contribution is zero on pad rows)
        const float4* pe = reinterpret_cast<const float4*>(pos_table + 1 * (size_t)Cdim);
        #pragma unroll
        for (int c = 0; c < VPT; c++) v[c] = pe[tid + NT * c];
        ln_frag(v, ln_e_g, ln_e_b, sm, tid);
        #pragma unroll
        for (int c = 0; c < VPT; c++)
            reinterpret_cast<float4*>(g_pad_out)[tid + NT * c] = v[c];
    }
}

// Kernel B: one row per CTA with fast copy paths for BOS and pad rows.
__global__ void __launch_bounds__(NT)
embed_kernel(const float* __restrict__ x,
             const int*   __restrict__ lengths,
             const float* __restrict__ pos_table,
             const float* __restrict__ scale_p,
             const float* __restrict__ ln_e_g,
             const float* __restrict__ ln_e_b,
             float* __restrict__ out,
             long long out_size) {
    const int row = blockIdx.x;
    const int tid = threadIdx.x;
    const int b   = row / T2;
    const int t2  = row % T2;
    const int l   = lengths[b];

    float4* orow = reinterpret_cast<float4*>(out + (size_t)row * Cdim);

    const long long XSZ = (long long)NROWS * Cdim;
    const bool aux  = (out_size >= XSZ + (long long)NROWS);
    const bool aux2 = (out_size >= XSZ + (long long)NROWS + Bdim);
    if (aux) {
        if (tid == 0) out[XSZ + row] = (t2 >= l + 2) ? 1.0f : 0.0f;
        if (tid == 1 && t2 == 0 && aux2)
            out[XSZ + (long long)NROWS + b] = (float)(l + 2);
    }

    if (t2 == 0) {
        // BOS row: precomputed
        const float4* src = reinterpret_cast<const float4*>(g_bos_out);
        #pragma unroll
        for (int c = 0; c < VPT; c++) orow[tid + NT * c] = src[tid + NT * c];
        return;
    }
    if (t2 >= l + 2) {
        // Pad row: precomputed (reads L1/L2-hot)
        const float4* src = reinterpret_cast<const float4*>(g_pad_out);
        #pragma unroll
        for (int c = 0; c < VPT; c++) orow[tid + NT * c] = src[tid + NT * c];
        return;
    }

    __shared__ float sm[4];
    const float sc = scale_p[0];

    float4 v[VPT];
    if (t2 == l + 1) {
        const float4* src = reinterpret_cast<const float4*>(g_eos_ln);
        #pragma unroll
        for (int c = 0; c < VPT; c++) v[c] = src[tid + NT * c];
    } else {
        const float4* xr = reinterpret_cast<const float4*>(
            x + ((size_t)(b * Tdim + (t2 - 1))) * Cdim);
        #pragma unroll
        for (int c = 0; c < VPT; c++) v[c] = xr[tid + NT * c];
    }

    // nonpad position row: t2 + 2
    const float4* per = reinterpret_cast<const float4*>(pos_table + (size_t)(t2 + 2) * Cdim);

    float s = 0.f, s2 = 0.f;
    #pragma unroll
    for (int c = 0; c < VPT; c++) {
        const float4 p = per[tid + NT * c];
        v[c].x = v[c].x * sc + p.x;
        v[c].y = v[c].y * sc + p.y;
        v[c].z = v[c].z * sc + p.z;
        v[c].w = v[c].w * sc + p.w;
        s  += v[c].x + v[c].y + v[c].z + v[c].w;
        s2 += v[c].x*v[c].x + v[c].y*v[c].y + v[c].z*v[c].z + v[c].w*v[c].w;
    }
    const float2 r = row_reduce64(s, s2, sm);
    const float mu  = r.x * (1.0f / Cdim);
    const float var = r.y * (1.0f / Cdim) - mu * mu;
    const float inv = rsqrtf(var + EPS);

    const float4* gg = reinterpret_cast<const float4*>(ln_e_g);
    const float4* bb = reinterpret_cast<const float4*>(ln_e_b);
    #pragma unroll
    for (int c = 0; c < VPT; c++) {
        const float4 g  = gg[tid + NT * c];
        const float4 bt = bb[tid + NT * c];
        float4 o;
        o.x = (v[c].x - mu) * inv * g.x + bt.x;
        o.y = (v[c].y - mu) * inv * g.y + bt.y;
        o.z = (v[c].z - mu) * inv * g.z + bt.z;
        o.w = (v[c].w - mu) * inv * g.w + bt.w;
        orow[tid + NT * c] = o;
    }
}

extern "C" void kernel_launch(void* const* d_in, const int* in_sizes, int n_in,
                              void* d_out, int out_size) {
    const float* x         = (const float*)d_in[0];
    const int*   lengths   = (const int*)  d_in[1];
    const float* bos_emb   = (const float*)d_in[2];
    const float* eos_emb   = (const float*)d_in[3];
    const float* ln_s_g    = (const float*)d_in[4];
    const float* ln_s_b    = (const float*)d_in[5];
    const float* pos_table = (const float*)d_in[6];
    const float* scale     = (const float*)d_in[7];
    const float* ln_e_g    = (const float*)d_in[8];
    const float* ln_e_b    = (const float*)d_in[9];
    float* out = (float*)d_out;

    precompute_kernel<<<3, NT>>>(bos_emb, eos_emb, ln_s_g, ln_s_b,
                                 pos_table, scale, ln_e_g, ln_e_b);
    embed_kernel<<<NROWS, NT>>>(x, lengths, pos_table, scale,
                                ln_e_g, ln_e_b, out, (long long)out_size);
}